// round 7
// baseline (speedup 1.0000x reference)
#include <cuda_runtime.h>
#include <cstdint>
#include <cstddef>

// Monarch embedding, analytically folded:
//   out[tok][kr*32+o] = (kr&1 == s) ? L[v*16 + kr/2] * R[(kr*32 + c)*32 + o] : 0
//   v = x[tok], k = v/786, s = k>>5, c = k&31.
//
// R7: stores moved off the LSU. STG.128 issue cost (~12cyc) x 886/SM was the
// hidden ~6us serial component. Now: compute -> STS.128 into smem (crossbar,
// ~4cyc, phase-conflict-free: each 8-lane phase hits one contiguous 128B row)
// -> one thread issues cp.async.bulk shared->global (TMA path, async).
// Double-buffered 2x8KB smem, persistent grid 1024 CTAs x 8 iters x 2 tokens.
// Warps parity-pure: warp w -> p=w>>2, rows kr = 2*(4*(w&3)+l/8) + p.

#define G    1024              // persistent CTAs (single wave @ 8/SM)
#define TOK  2                 // tokens per iteration
#define NIT  8                 // iterations: G*NIT*TOK = 16384 tokens
#define ROW  1024              // floats per token row
#define BULK_BYTES (TOK * ROW * 4)   // 8192

__global__ void __launch_bounds__(256) monarch_embed_kernel(
    const int* __restrict__ x,
    const float* __restrict__ L,
    const float* __restrict__ R,
    float* __restrict__ out)
{
    __shared__ float buf[2][TOK * ROW];    // 16 KB

    const int tid = threadIdx.x;
    const int w   = tid >> 5;
    const int l   = tid & 31;
    const int p   = w >> 2;                // warp parity (0/1)
    const int q   = w & 3;
    const int r   = l >> 3;
    const int o   = (l & 7) << 2;
    const int i   = (q << 2) + r;          // 0..15
    const int kr  = (i << 1) + p;          // 0..31
    const int slot = (kr << 5) + o;

    const int bid = blockIdx.x;
    const int2* xp = reinterpret_cast<const int2*>(x) + bid;   // int2 = 2 tokens

    uint32_t sm_base;
    asm("{ .reg .u64 t; cvta.to.shared.u64 t, %1; cvt.u32.u64 %0, t; }"
        : "=r"(sm_base) : "l"((void*)buf));

    // Prologue: iter-0 x in flight.
    int2 xc = __ldg(xp);
    int  b  = 0;

#pragma unroll 1
    for (int j = 0; j < NIT; j++) {
        // Prefetch next x (clamped -> always in-bounds).
        const int jn = (j + 1 < NIT) ? (j + 1) : (NIT - 1);
        int2 xn = __ldg(xp + jn * G);

        // Fire long-latency L gathers for current iteration.
        float lv0 = __ldg(&L[(size_t)xc.x * 16 + i]);
        float lv1 = __ldg(&L[(size_t)xc.y * 16 + i]);

        // Backpressure: buffer b was handed to TMA at iter j-2; ensure that
        // bulk copy has consumed it before we overwrite.
        if (j >= 2 && tid == 0)
            asm volatile("cp.async.bulk.wait_group 1;" ::: "memory");
        __syncthreads();

        // Compute + STS (phase-conflict-free STS.128).
        const int vs[TOK] = {xc.x, xc.y};
        const float lvs[TOK] = {lv0, lv1};
#pragma unroll
        for (int t = 0; t < TOK; t++) {
            const int k = vs[t] / 786;
            const int s = k >> 5;
            const int c = k & 31;
            const float4 r4 = *reinterpret_cast<const float4*>(
                &R[((size_t)((kr << 5) + c) << 5) + o]);
            const float lvv = (s == p) ? lvs[t] : 0.0f;   // SEL, no branch
            const float4 res = make_float4(lvv * r4.x, lvv * r4.y,
                                           lvv * r4.z, lvv * r4.w);
            *reinterpret_cast<float4*>(&buf[b][t * ROW + slot]) = res;
        }
        __syncthreads();

        // Hand the filled buffer to the async (TMA) proxy.
        if (tid == 0) {
            asm volatile("fence.proxy.async.shared::cta;" ::: "memory");
            float* gdst = out + ((size_t)(j * G + bid) * TOK) * ROW;
            uint32_t ssrc = sm_base + (uint32_t)(b * BULK_BYTES);
            asm volatile(
                "cp.async.bulk.global.shared::cta.bulk_group [%0], [%1], %2;"
                :: "l"(gdst), "r"(ssrc), "r"((uint32_t)BULK_BYTES) : "memory");
            asm volatile("cp.async.bulk.commit_group;" ::: "memory");
        }

        xc = xn;
        b ^= 1;
    }

    // Drain outstanding bulk copies before exit.
    if (tid == 0)
        asm volatile("cp.async.bulk.wait_group 0;" ::: "memory");
}

extern "C" void kernel_launch(void* const* d_in, const int* in_sizes, int n_in,
                              void* d_out, int out_size) {
    const int*   x = (const int*)  d_in[0];   // (8, 2048) int32
    const float* L = (const float*)d_in[1];   // (64, 786, 16) f32
    const float* R = (const float*)d_in[2];   // (32, 32, 32) f32
    // d_in[3] = p : analytically folded (perfect_shuffle(64, 1024))

    monarch_embed_kernel<<<G, 256>>>(x, L, R, (float*)d_out);
}

// round 8
// speedup vs baseline: 1.5021x; 1.5021x over previous
#include <cuda_runtime.h>
#include <cstddef>

// Monarch embedding, analytically folded:
//   out[tok][kr*32+o] = (kr&1 == s) ? L[v*16 + kr/2] * R[(kr*32 + c)*32 + o] : 0
//   v = x[tok], k = v/786, s = k>>5, c = k&31.
//
// R8: anti-front-batch. R5's 5-deep front-batched LDG block at oe=8 trips the
// B300 cross-CTA L1tex-queue spread (oe*MLP_p1=40 >> 16 -> spr~1.5x). Here the
// L gathers roll as a depth-2 pipeline over token PAIRS inside a no-unroll
// loop with register rotation (loop-carried dep stops ptxas re-hoisting).
// Front batch is now just x + 2 L loads. Everything else = R5: T=4 tokens/CTA,
// 4096 one-shot CTAs, parity-pure warps, branch-free SEL, L1-hot R float4,
// fully-coalesced STG.128. Target regs <= 32 (8 CTAs/SM).
// Warps parity-pure: warp w -> p=w>>2, rows kr = 2*(4*(w&3)+l/8) + p.

__global__ void __launch_bounds__(256) monarch_embed_kernel(
    const int* __restrict__ x,
    const float* __restrict__ L,
    const float* __restrict__ R,
    float* __restrict__ out)
{
    const int tb  = blockIdx.x << 2;       // 4 tokens per CTA
    const int tid = threadIdx.x;
    const int w   = tid >> 5;
    const int l   = tid & 31;
    const int p   = w >> 2;                // warp parity (0/1)
    const int q   = w & 3;
    const int r   = l >> 3;
    const int o   = (l & 7) << 2;
    const int i   = (q << 2) + r;          // 0..15
    const int kr  = (i << 1) + p;          // 0..31
    const int slot = (kr << 5) + o;

    // One aligned 128-bit load covers x for all 4 tokens.
    const int4 xv = *reinterpret_cast<const int4*>(x + tb);

    // Pipeline registers: current pair (va,vb,la,lb), upcoming pair (vc,vd).
    int   va = xv.x, vb = xv.y, vc = xv.z, vd = xv.w;
    float la = __ldg(&L[(size_t)va * 16 + i]);
    float lb = __ldg(&L[(size_t)vb * 16 + i]);

    float* ob = out + (size_t)tb * 1024 + slot;

#pragma unroll 1
    for (int jj = 0; jj < 2; jj++) {
        // Prefetch next pair's L (iter 1 re-loads same addrs -> L1 hits; cheap).
        const float ln0 = __ldg(&L[(size_t)vc * 16 + i]);
        const float ln1 = __ldg(&L[(size_t)vd * 16 + i]);

        // Consume current pair.
        {
            const int k = va / 786;
            const int s = k >> 5;
            const int c = k & 31;
            const float4 r4 = *reinterpret_cast<const float4*>(
                &R[((size_t)((kr << 5) + c) << 5) + o]);
            const float lvv = (s == p) ? la : 0.0f;   // SEL, no branch
            *reinterpret_cast<float4*>(ob) =
                make_float4(lvv * r4.x, lvv * r4.y, lvv * r4.z, lvv * r4.w);
        }
        {
            const int k = vb / 786;
            const int s = k >> 5;
            const int c = k & 31;
            const float4 r4 = *reinterpret_cast<const float4*>(
                &R[((size_t)((kr << 5) + c) << 5) + o]);
            const float lvv = (s == p) ? lb : 0.0f;   // SEL, no branch
            *reinterpret_cast<float4*>(ob + 1024) =
                make_float4(lvv * r4.x, lvv * r4.y, lvv * r4.z, lvv * r4.w);
        }

        // Rotate pipeline.
        va = vc; vb = vd;
        la = ln0; lb = ln1;
        ob += 2048;
    }
}

extern "C" void kernel_launch(void* const* d_in, const int* in_sizes, int n_in,
                              void* d_out, int out_size) {
    const int*   x = (const int*)  d_in[0];   // (8, 2048) int32
    const float* L = (const float*)d_in[1];   // (64, 786, 16) f32
    const float* R = (const float*)d_in[2];   // (32, 32, 32) f32
    // d_in[3] = p : analytically folded (perfect_shuffle(64, 1024))

    const int ntok = out_size / 1024;         // 16384 tokens
    monarch_embed_kernel<<<ntok / 4, 256>>>(x, L, R, (float*)d_out);
}

// round 9
// speedup vs baseline: 1.5617x; 1.0396x over previous
#include <cuda_runtime.h>
#include <cstdint>
#include <cstddef>

// Monarch embedding, analytically folded:
//   out[tok][kr*32+o] = (kr&1 == s) ? L[v*16 + kr/2] * R[(kr*32 + c)*32 + o] : 0
//   v = x[tok], k = v/786, s = k>>5, c = k&31.
//
// R9: 256-bit memory ops (sm_100+). Each thread owns a 32B chunk (8 floats)
// of one token row: 128 threads cover a 4KB row. Per token: 1 scalar L load,
// 1 LDG.256 (R), 8 FMUL, 1 STG.256. Store/LDG instruction count halves vs
// the float4 scheme; bytes unchanged. 4 tokens/CTA (2 passes x 2 tokens),
// grid 4096, branch-free SEL parity (intra-warp divergence-free).
// Thread map: th = tid>>7 (token of pair), slot = tid&127,
//   kr = slot>>2 (row 0..31), osub = (slot&3)*8, i = kr>>1, p = kr&1.

__global__ void __launch_bounds__(256) monarch_embed_kernel(
    const int* __restrict__ x,
    const float* __restrict__ L,
    const float* __restrict__ R,
    float* __restrict__ out)
{
    const int tb   = blockIdx.x << 2;      // 4 tokens per CTA
    const int tid  = threadIdx.x;
    const int th   = tid >> 7;             // 0/1: which token of each pair
    const int slot = tid & 127;
    const int kr   = slot >> 2;            // 0..31
    const int osub = (slot & 3) << 3;      // 0,8,16,24
    const int i    = kr >> 1;              // 0..15  (L column)
    const int p    = kr & 1;               // row parity

    // One aligned 128-bit load covers x for all 4 tokens.
    const int4 xv = *reinterpret_cast<const int4*>(x + tb);
    const int v0 = th ? xv.y : xv.x;       // pass-0 token
    const int v1 = th ? xv.w : xv.z;       // pass-1 token

    // Fire both long-latency L gathers up front (2 scalar regs).
    const float lva = __ldg(&L[(size_t)v0 * 16 + i]);
    const float lvb = __ldg(&L[(size_t)v1 * 16 + i]);

    const int rowoff = (kr << 5) + osub;
    float* ob = out + (size_t)(tb + th) * 1024 + rowoff;

#pragma unroll
    for (int m = 0; m < 2; m++) {
        const int   v   = m ? v1  : v0;
        const float lvf = m ? lvb : lva;
        const int k = v / 786;
        const int s = k >> 5;
        const int c = k & 31;

        const float* rp = &R[((size_t)((kr << 5) + c) << 5) + osub];
        float r0, r1, r2, r3, r4, r5, r6, r7;
        asm("ld.global.v8.f32 {%0,%1,%2,%3,%4,%5,%6,%7}, [%8];"
            : "=f"(r0), "=f"(r1), "=f"(r2), "=f"(r3),
              "=f"(r4), "=f"(r5), "=f"(r6), "=f"(r7)
            : "l"(rp));

        const float lvv = (s == p) ? lvf : 0.0f;   // SEL, no branch
        r0 *= lvv; r1 *= lvv; r2 *= lvv; r3 *= lvv;
        r4 *= lvv; r5 *= lvv; r6 *= lvv; r7 *= lvv;

        float* op = ob + (size_t)m * 2048;          // pass-1 token = tb+2+th
        asm volatile("st.global.v8.f32 [%0], {%1,%2,%3,%4,%5,%6,%7,%8};"
            :: "l"(op),
               "f"(r0), "f"(r1), "f"(r2), "f"(r3),
               "f"(r4), "f"(r5), "f"(r6), "f"(r7)
            : "memory");
    }
}

extern "C" void kernel_launch(void* const* d_in, const int* in_sizes, int n_in,
                              void* d_out, int out_size) {
    const int*   x = (const int*)  d_in[0];   // (8, 2048) int32
    const float* L = (const float*)d_in[1];   // (64, 786, 16) f32
    const float* R = (const float*)d_in[2];   // (32, 32, 32) f32
    // d_in[3] = p : analytically folded (perfect_shuffle(64, 1024))

    const int ntok = out_size / 1024;         // 16384 tokens
    monarch_embed_kernel<<<ntok / 4, 256>>>(x, L, R, (float*)d_out);
}